// round 4
// baseline (speedup 1.0000x reference)
#include <cuda_runtime.h>
#include <cuda_bf16.h>
#include <cstdint>
#include <math.h>

#define Bsz  2
#define Nseq 2048
#define Dm   512
#define Hh   8
#define DHd  512
#define Ff   4096
#define Mrows 4096   // Bsz*Nseq
#define BH   16      // Bsz*Hh

// ======================= scratch (device globals) ===========================
__device__ __align__(16) __nv_bfloat16 g_Xh[(size_t)Mrows * Dm];
__device__ __align__(16) __nv_bfloat16 g_Xl[(size_t)Mrows * Dm];
__device__ __align__(16) __nv_bfloat16 g_WTh[3 * (size_t)Ff * Dm];   // [mode][n][k]
__device__ __align__(16) __nv_bfloat16 g_WTl[3 * (size_t)Ff * Dm];
__device__ __align__(16) __nv_bfloat16 g_WoTh[(size_t)Dm * Dm];
__device__ __align__(16) __nv_bfloat16 g_WoTl[(size_t)Dm * Dm];
__device__ __align__(16) __nv_bfloat16 g_Qh[(size_t)Mrows * Ff];
__device__ __align__(16) __nv_bfloat16 g_Ql[(size_t)Mrows * Ff];
__device__ __align__(16) __nv_bfloat16 g_Kh[(size_t)Mrows * Ff];
__device__ __align__(16) __nv_bfloat16 g_Kl[(size_t)Mrows * Ff];
__device__ __align__(16) __nv_bfloat16 g_Vh[(size_t)Mrows * Ff];
__device__ __align__(16) __nv_bfloat16 g_Vl[(size_t)Mrows * Ff];
__device__ __align__(16) float         g_YH[(size_t)BH * Nseq * Dm];
__device__ __align__(16) __nv_bfloat16 g_Gh[(size_t)Mrows * Dm];
__device__ __align__(16) __nv_bfloat16 g_Gl[(size_t)Mrows * Dm];

// ======================= helpers ===========================================
__device__ __forceinline__ uint32_t smem_to_u32(const void* p) {
    uint32_t a;
    asm("{ .reg .u64 t; cvta.to.shared.u64 t, %1; cvt.u32.u64 %0, t; }" : "=r"(a) : "l"(p));
    return a;
}
#define SWZ(b) ((b) ^ (((b) >> 3) & 0x70))

#define LDSM_X4(r, addr) \
    asm volatile("ldmatrix.sync.aligned.m8n8.x4.shared.b16 {%0,%1,%2,%3}, [%4];" \
        : "=r"((r)[0]), "=r"((r)[1]), "=r"((r)[2]), "=r"((r)[3]) : "r"(addr))
#define LDSM_X4_T(r, addr) \
    asm volatile("ldmatrix.sync.aligned.m8n8.x4.trans.shared.b16 {%0,%1,%2,%3}, [%4];" \
        : "=r"((r)[0]), "=r"((r)[1]), "=r"((r)[2]), "=r"((r)[3]) : "r"(addr))

#define MMA_BF16(d, a, b0, b1) \
    asm volatile("mma.sync.aligned.m16n8k16.row.col.f32.bf16.bf16.f32 " \
        "{%0,%1,%2,%3}, {%4,%5,%6,%7}, {%8,%9}, {%0,%1,%2,%3};" \
        : "+f"((d)[0]), "+f"((d)[1]), "+f"((d)[2]), "+f"((d)[3]) \
        : "r"((a)[0]), "r"((a)[1]), "r"((a)[2]), "r"((a)[3]), "r"(b0), "r"(b1))

#define CP_ASYNC16(dst, src) \
    asm volatile("cp.async.cg.shared.global [%0], [%1], 16;" :: "r"(dst), "l"(src))
#define CP_COMMIT() asm volatile("cp.async.commit_group;")
#define CP_WAIT1()  asm volatile("cp.async.wait_group 1;")
#define CP_WAIT0()  asm volatile("cp.async.wait_group 0;")

// ======================= bf16 split helpers =================================
__device__ __forceinline__ unsigned bf2(float a, float b) {
    return (unsigned)__bfloat16_as_ushort(__float2bfloat16(a)) |
           ((unsigned)__bfloat16_as_ushort(__float2bfloat16(b)) << 16);
}
__device__ __forceinline__ void split_pair(float a, float b, unsigned& h, unsigned& l) {
    __nv_bfloat16 ah = __float2bfloat16(a), bh = __float2bfloat16(b);
    h = (unsigned)__bfloat16_as_ushort(ah) | ((unsigned)__bfloat16_as_ushort(bh) << 16);
    l = bf2(a - __bfloat162float(ah), b - __bfloat162float(bh));
}
__device__ __forceinline__ void split1(float a, __nv_bfloat16& h, __nv_bfloat16& l) {
    h = __float2bfloat16(a);
    l = __float2bfloat16(a - __bfloat162float(h));
}

// ======================= generic mma.sync GEMM core (proj/out) ==============
#define STAGE_BYTES 65536
#define SMEM_BYTES  (2 * STAGE_BYTES)

__device__ __forceinline__ void mma_chunk(uint32_t sst, int lane, int wm, int wn,
                                          float (&acc)[4][4][4]) {
    const uint32_t aH = sst, aL = sst + 16384, bB = sst + 32768, bL = sst + 49152;
#pragma unroll
    for (int kk = 0; kk < 4; kk++) {
        uint32_t ah[4][4], al[4][4], bh[2][4], bl[2][4];
        const int arow = wm * 64 + (lane & 15);
        const int acolb = kk * 32 + ((lane >> 4) << 4);
#pragma unroll
        for (int mi = 0; mi < 4; mi++) {
            uint32_t off = SWZ(((arow + mi * 16) << 7) + acolb);
            LDSM_X4(ah[mi], aH + off);
            LDSM_X4(al[mi], aL + off);
        }
        const int brow = wn * 32 + (lane & 7) + ((lane >> 4) << 3);
        const int bcolb = kk * 32 + (((lane >> 3) & 1) << 4);
#pragma unroll
        for (int nb = 0; nb < 2; nb++) {
            uint32_t off = SWZ(((brow + nb * 16) << 7) + bcolb);
            LDSM_X4(bh[nb], bB + off);
            LDSM_X4(bl[nb], bL + off);
        }
#pragma unroll
        for (int mi = 0; mi < 4; mi++)
#pragma unroll
            for (int ni = 0; ni < 4; ni++) {
                const int nb = ni >> 1, p = (ni & 1) << 1;
                MMA_BF16(acc[mi][ni], ah[mi], bh[nb][p], bh[nb][p + 1]);
                MMA_BF16(acc[mi][ni], ah[mi], bl[nb][p], bl[nb][p + 1]);
                MMA_BF16(acc[mi][ni], al[mi], bh[nb][p], bh[nb][p + 1]);
            }
    }
}

__device__ __forceinline__ void issue_chunk(
    uint32_t sbase, int c, int t,
    const __nv_bfloat16* Ah, const __nv_bfloat16* Al, size_t sA,
    const __nv_bfloat16* Bh, const __nv_bfloat16* Bl, size_t sB)
{
    const uint32_t sst = sbase + (uint32_t)(c & 1) * STAGE_BYTES;
    const __nv_bfloat16* srcs[4] = {Ah + (c << 6), Al + (c << 6), Bh + (c << 6), Bl + (c << 6)};
    const size_t str[4] = {sA, sA, sB, sB};
#pragma unroll
    for (int i = 0; i < 16; i++) {
        const int tile = i >> 2;
        const int u = ((i & 3) << 8) + t;
        const int r = u >> 3, cu = u & 7;
        uint32_t dst = sst + tile * 16384 + SWZ((r << 7) + (cu << 4));
        const void* src = srcs[tile] + (size_t)r * str[tile] + (cu << 3);
        CP_ASYNC16(dst, src);
    }
    CP_COMMIT();
}

__device__ __forceinline__ void gemm_mma(
    const __nv_bfloat16* Ah, const __nv_bfloat16* Al, size_t sA,
    const __nv_bfloat16* Bh, const __nv_bfloat16* Bl, size_t sB,
    int K, uint32_t sbase, float (&acc)[4][4][4])
{
    const int t = threadIdx.x;
    const int lane = t & 31, w = t >> 5, wm = w & 1, wn = w >> 1;
#pragma unroll
    for (int mi = 0; mi < 4; mi++)
#pragma unroll
        for (int ni = 0; ni < 4; ni++)
#pragma unroll
            for (int r = 0; r < 4; r++) acc[mi][ni][r] = 0.f;

    const int NC = K >> 6;
    issue_chunk(sbase, 0, t, Ah, Al, sA, Bh, Bl, sB);
    for (int c = 0; c < NC; c++) {
        if (c + 1 < NC) {
            issue_chunk(sbase, c + 1, t, Ah, Al, sA, Bh, Bl, sB);
            CP_WAIT1();
        } else {
            CP_WAIT0();
        }
        __syncthreads();
        mma_chunk(sbase + (uint32_t)(c & 1) * STAGE_BYTES, lane, wm, wn, acc);
        __syncthreads();
    }
}

// ======================= prep kernels =======================================
__global__ __launch_bounds__(256) void xc_kernel(const float* __restrict__ x) {
    int i = blockIdx.x * 256 + threadIdx.x;
    float4 v = ((const float4*)x)[i];
    unsigned h0, l0, h1, l1;
    split_pair(v.x, v.y, h0, l0);
    split_pair(v.z, v.w, h1, l1);
    ((uint2*)g_Xh)[i] = make_uint2(h0, h1);
    ((uint2*)g_Xl)[i] = make_uint2(l0, l1);
}

__global__ void wt_kernel(const float* __restrict__ src, __nv_bfloat16* dh,
                          __nv_bfloat16* dl, int K, int NC) {
    __shared__ float tile[32][33];
    int n0 = blockIdx.x * 32, k0 = blockIdx.y * 32;
    int tx = threadIdx.x, ty = threadIdx.y;
    tile[ty][tx] = src[(size_t)(k0 + ty) * NC + n0 + tx];
    __syncthreads();
    float v = tile[tx][ty];
    __nv_bfloat16 h, l;
    split1(v, h, l);
    size_t di = (size_t)(n0 + ty) * K + k0 + tx;
    dh[di] = h; dl[di] = l;
}

// ======================= 1) QKV projection GEMM + RoPE/bias epilogue ========
__global__ __launch_bounds__(256) void mm_proj_kernel(
    const float* __restrict__ cosr, const float* __restrict__ sinr,
    const float* __restrict__ bv)
{
    extern __shared__ __align__(128) char smem[];
    uint32_t sb = smem_to_u32(smem);
    const int mode = blockIdx.z;
    const int bm = blockIdx.y * 128, bn = blockIdx.x * 128;
    const __nv_bfloat16* Ah = g_Xh + (size_t)bm * Dm;
    const __nv_bfloat16* Al = g_Xl + (size_t)bm * Dm;
    const __nv_bfloat16* Bh = g_WTh + ((size_t)mode * Ff + bn) * Dm;
    const __nv_bfloat16* Bl = g_WTl + ((size_t)mode * Ff + bn) * Dm;
    float acc[4][4][4];
    gemm_mma(Ah, Al, Dm, Bh, Bl, Dm, Dm, sb, acc);

    const int t = threadIdx.x, lane = t & 31, w = t >> 5, wm = w & 1, wn = w >> 1;
    if (mode == 2) {
#pragma unroll
        for (int mi = 0; mi < 4; mi++)
#pragma unroll
            for (int ni = 0; ni < 4; ni++) {
                int m = bm + wm * 64 + mi * 16 + (lane >> 2);
                int c = bn + wn * 32 + ni * 8 + ((lane & 3) << 1);
                float b0 = bv[c], b1 = bv[c + 1];
#pragma unroll
                for (int half = 0; half < 2; half++) {
                    int mm = m + half * 8;
                    unsigned hw, lw;
                    split_pair(acc[mi][ni][half * 2] + b0, acc[mi][ni][half * 2 + 1] + b1, hw, lw);
                    *(unsigned*)&g_Vh[(size_t)mm * Ff + c] = hw;
                    *(unsigned*)&g_Vl[(size_t)mm * Ff + c] = lw;
                }
            }
    } else {
        __nv_bfloat16* OH = (mode == 0) ? g_Qh : g_Kh;
        __nv_bfloat16* OL = (mode == 0) ? g_Ql : g_Kl;
#pragma unroll
        for (int mi = 0; mi < 4; mi++)
#pragma unroll
            for (int ni = 0; ni < 4; ni++) {
                int m0 = bm + wm * 64 + mi * 16 + (lane >> 2);
                int c = bn + wn * 32 + ni * 8 + ((lane & 3) << 1);
#pragma unroll
                for (int half = 0; half < 2; half++) {
                    int m = m0 + half * 8;
                    int n = m & (Nseq - 1);
                    float cr0 = cosr[(size_t)n * Ff + c];
                    float sr0 = sinr[(size_t)n * Ff + c];
                    float cr1 = cosr[(size_t)n * Ff + c + 1];
                    float sr1 = sinr[(size_t)n * Ff + c + 1];
                    float e = acc[mi][ni][half * 2];
                    float o = acc[mi][ni][half * 2 + 1];
                    float oe = e * cr0 - o * sr0;
                    float oo = o * cr1 + e * sr1;
                    unsigned hw, lw;
                    split_pair(oe, oo, hw, lw);
                    *(unsigned*)&OH[(size_t)m * Ff + c] = hw;
                    *(unsigned*)&OL[(size_t)m * Ff + c] = lw;
                }
            }
    }
}

// ======================= 2) fused flash attention ===========================
#define IB 64
#define OFF_M    0
#define OFF_L    256
#define OFF_MRED 512
#define OFF_LRED 1536
#define OFF_P    4096
#define OFF_SBUF 36864
#define SSTAGE   49152
#define SOFF_QH  0
#define SOFF_QL  8192
#define SOFF_KH  16384
#define SOFF_KL  32768
#define OFF_VBUF 135168
#define VSTAGE   32768
#define FUSED_SMEM 200704

__device__ __forceinline__ void issue_S_chunk(uint32_t sst, int t,
    const __nv_bfloat16* Qh, const __nv_bfloat16* Ql,
    const __nv_bfloat16* Kh, const __nv_bfloat16* Kl)
{
#pragma unroll
    for (int i = 0; i < 2; i++) {
        int u = t + (i << 8), r = u >> 3, cu = u & 7;
        uint32_t d = sst + SOFF_QH + SWZ((r << 7) + (cu << 4));
        CP_ASYNC16(d, Qh + (size_t)r * Ff + (cu << 3));
        CP_ASYNC16(d + (SOFF_QL - SOFF_QH), Ql + (size_t)r * Ff + (cu << 3));
    }
#pragma unroll
    for (int i = 0; i < 4; i++) {
        int u = t + (i << 8), r = u >> 3, cu = u & 7;
        uint32_t d = sst + SOFF_KH + SWZ((r << 7) + (cu << 4));
        CP_ASYNC16(d, Kh + (size_t)r * Ff + (cu << 3));
        CP_ASYNC16(d + (SOFF_KL - SOFF_KH), Kl + (size_t)r * Ff + (cu << 3));
    }
}

// V chunk: 16 tokens x 512 dh (hi+lo) = 32KB; layout [hi/lo][panel 8][tok 16][128B]
__device__ __forceinline__ void issue_V_chunk(uint32_t vst, int t,
    const __nv_bfloat16* Vh, const __nv_bfloat16* Vl)
{
#pragma unroll
    for (int i = 0; i < 4; i++) {
        int u = t + (i << 8);                  // 0..1023
        int panel = u >> 7, r = (u >> 3) & 15, cu = u & 7;
        uint32_t d = vst + panel * 2048 + SWZ((r << 7) + (cu << 4));
        CP_ASYNC16(d, Vh + (size_t)r * Ff + panel * 64 + (cu << 3));
        CP_ASYNC16(d + 16384, Vl + (size_t)r * Ff + panel * 64 + (cu << 3));
    }
}

__device__ __forceinline__ void s_mma_chunk(uint32_t sst, int lane, int wm, int wn,
                                            float (&acc)[2][4][4]) {
    const uint32_t qh = sst + SOFF_QH, ql = sst + SOFF_QL;
    const uint32_t kh = sst + SOFF_KH, kl = sst + SOFF_KL;
#pragma unroll
    for (int kk = 0; kk < 4; kk++) {
        uint32_t ah[2][4], al[2][4], bh[2][4], bl[2][4];
        const int acb = kk * 32 + ((lane >> 4) << 4);
#pragma unroll
        for (int mi = 0; mi < 2; mi++) {
            uint32_t off = SWZ(((wm * 32 + mi * 16 + (lane & 15)) << 7) + acb);
            LDSM_X4(ah[mi], qh + off);
            LDSM_X4(al[mi], ql + off);
        }
        const int brow = wn * 32 + (lane & 7) + ((lane >> 4) << 3);
        const int bcb = kk * 32 + (((lane >> 3) & 1) << 4);
#pragma unroll
        for (int nb = 0; nb < 2; nb++) {
            uint32_t off = SWZ(((brow + nb * 16) << 7) + bcb);
            LDSM_X4(bh[nb], kh + off);
            LDSM_X4(bl[nb], kl + off);
        }
#pragma unroll
        for (int mi = 0; mi < 2; mi++)
#pragma unroll
            for (int ni = 0; ni < 4; ni++) {
                const int nb = ni >> 1, p = (ni & 1) << 1;
                MMA_BF16(acc[mi][ni], ah[mi], bh[nb][p], bh[nb][p + 1]);
                MMA_BF16(acc[mi][ni], ah[mi], bl[nb][p], bl[nb][p + 1]);
                MMA_BF16(acc[mi][ni], al[mi], bh[nb][p], bh[nb][p + 1]);
            }
    }
}

__device__ __forceinline__ void pv_mma_chunk(uint32_t sb, uint32_t vst, int vc,
                                             int lane, int wm, int wn,
                                             float (&accO)[2][16][4]) {
    uint32_t ah[2][4], al[2][4];
    const int pp = vc >> 2;
    const int pcb = (vc & 3) * 32 + ((lane >> 4) << 4);
#pragma unroll
    for (int mi = 0; mi < 2; mi++) {
        uint32_t off = SWZ(((wm * 32 + mi * 16 + (lane & 15)) << 7) + pcb);
        LDSM_X4(ah[mi], sb + OFF_P + pp * 8192 + off);
        LDSM_X4(al[mi], sb + OFF_P + 16384 + pp * 8192 + off);
    }
    const int tok = (lane & 7) + ((lane >> 3) & 1) * 8;
#pragma unroll
    for (int np = 0; np < 8; np++) {
        const int panel = 2 * wn + (np >> 2);
        const int dhb = (np & 3) * 16 + ((lane >> 4) << 3);
        uint32_t off = panel * 2048 + SWZ((tok << 7) + (dhb << 1));
        uint32_t vbh[4], vbl[4];
        LDSM_X4_T(vbh, vst + off);
        LDSM_X4_T(vbl, vst + 16384 + off);
#pragma unroll
        for (int mi = 0; mi < 2; mi++)
#pragma unroll
            for (int q = 0; q < 2; q++) {
                float* d = accO[mi][np * 2 + q];
                MMA_BF16(d, ah[mi], vbh[q * 2], vbh[q * 2 + 1]);
                MMA_BF16(d, ah[mi], vbl[q * 2], vbl[q * 2 + 1]);
                MMA_BF16(d, al[mi], vbh[q * 2], vbh[q * 2 + 1]);
            }
    }
}

__global__ __launch_bounds__(256, 1) void fused_attn_kernel() {
    extern __shared__ __align__(128) char smem[];
    const uint32_t sb = smem_to_u32(smem);
    float* sm_m = (float*)(smem + OFF_M);
    float* sm_l = (float*)(smem + OFF_L);
    float* mred = (float*)(smem + OFF_MRED);   // [4][64]
    float* lred = (float*)(smem + OFF_LRED);   // [4][64]

    const int ib = 31 - blockIdx.x;            // heavy blocks first
    const int bh = blockIdx.y;
    const int b = bh >> 3, h = bh & 7;
    const int i0 = ib * IB;
    const int jlast = ib >> 1;
    const int t = threadIdx.x, lane = t & 31, w = t >> 5;
    const int wm = w & 1, wn = w >> 1;

    if (t < 64) { sm_m[t] = -1e30f; sm_l[t] = 0.f; }
    __syncthreads();

    const size_t colQ = (size_t)h * DHd;
    const __nv_bfloat16* Qh0 = g_Qh + (size_t)(b * Nseq + i0) * Ff + colQ;
    const __nv_bfloat16* Ql0 = g_Ql + (size_t)(b * Nseq + i0) * Ff + colQ;

    float accO[2][16][4];
#pragma unroll
    for (int mi = 0; mi < 2; mi++)
#pragma unroll
        for (int ni = 0; ni < 16; ni++)
#pragma unroll
            for (int v = 0; v < 4; v++) accO[mi][ni][v] = 0.f;

    const int r0 = wm * 32 + (lane >> 2);

    for (int jb = 0; jb <= jlast; jb++) {
        const int j0 = jb << 7;
        const size_t krow0 = (size_t)(b * Nseq + j0);
        const __nv_bfloat16* Kh0 = g_Kh + krow0 * Ff + colQ;
        const __nv_bfloat16* Kl0 = g_Kl + krow0 * Ff + colQ;
        const __nv_bfloat16* Vh0 = g_Vh + krow0 * Ff + colQ;
        const __nv_bfloat16* Vl0 = g_Vl + krow0 * Ff + colQ;

        float accS[2][4][4];
#pragma unroll
        for (int mi = 0; mi < 2; mi++)
#pragma unroll
            for (int ni = 0; ni < 4; ni++)
#pragma unroll
                for (int v = 0; v < 4; v++) accS[mi][ni][v] = 0.f;

        // ---- S = Q K^T over 8 k-chunks of 64, double-buffered ----
        issue_V_chunk(sb + OFF_VBUF, t, Vh0, Vl0);   // V chunk0 joins group 0
        issue_S_chunk(sb + OFF_SBUF, t, Qh0, Ql0, Kh0, Kl0);
        CP_COMMIT();
        for (int c = 0; c < 8; c++) {
            if (c + 1 < 8) {
                issue_S_chunk(sb + OFF_SBUF + ((c + 1) & 1) * SSTAGE, t,
                              Qh0 + ((c + 1) << 6), Ql0 + ((c + 1) << 6),
                              Kh0 + ((c + 1) << 6), Kl0 + ((c + 1) << 6));
                CP_COMMIT();
                CP_WAIT1();
            } else {
                CP_WAIT0();
            }
            __syncthreads();
            s_mma_chunk(sb + OFF_SBUF + (c & 1) * SSTAGE, lane, wm, wn, accS);
            __syncthreads();
        }

        // ---- causal mask (diagonal j-block only) ----
        if (jb == jlast) {
#pragma unroll
            for (int mi = 0; mi < 2; mi++)
#pragma unroll
                for (int ni = 0; ni < 4; ni++)
#pragma unroll
                    for (int v = 0; v < 4; v++) {
                        int rg = i0 + wm * 32 + mi * 16 + (lane >> 2) + ((v >> 1) << 3);
                        int cg = j0 + wn * 32 + ni * 8 + ((lane & 3) << 1) + (v & 1);
                        if (cg > rg) accS[mi][ni][v] = -1e30f;
                    }
        }

        // ---- online softmax ----
        float lmax[4];
#pragma unroll
        for (int rs = 0; rs < 4; rs++) {
            const int mi = rs >> 1, hf = rs & 1;
            float m = -1e30f;
#pragma unroll
            for (int ni = 0; ni < 4; ni++) {
                m = fmaxf(m, fmaxf(accS[mi][ni][hf * 2], accS[mi][ni][hf * 2 + 1]));
            }
            lmax[rs] = m;
        }
#pragma unroll
        for (int x = 1; x <= 2; x <<= 1)
#pragma unroll
            for (int rs = 0; rs < 4; rs++)
                lmax[rs] = fmaxf(lmax[rs], __shfl_xor_sync(0xffffffffu, lmax[rs], x));
        if ((lane & 3) == 0) {
#pragma unroll
            for (int rs = 0; rs < 4; rs++)
                mred[wn * 64 + r0 + (rs >> 1) * 16 + (rs & 1) * 8] = lmax[rs];
        }
        __syncthreads();

        float Mn[4], alpha[4];
#pragma unroll
        for (int rs = 0; rs < 4; rs++) {
            const int r = r0 + (rs >> 1) * 16 + (rs & 1) * 8;
            float bm = fmaxf(fmaxf(mred[r], mred[64 + r]), fmaxf(mred[128 + r], mred[192 + r]));
            float mo = sm_m[r];
            float mn = fmaxf(mo, bm);
            Mn[rs] = mn;
            alpha[rs] = __expf(mo - mn);
        }

        float lsum[4] = {0.f, 0.f, 0.f, 0.f};
#pragma unroll
        for (int mi = 0; mi < 2; mi++)
#pragma unroll
            for (int ni = 0; ni < 4; ni++)
#pragma unroll
                for (int hf = 0; hf < 2; hf++) {
                    const int rs = mi * 2 + hf;
                    float p0 = __expf(accS[mi][ni][hf * 2] - Mn[rs]);
                    float p1 = __expf(accS[mi][ni][hf * 2 + 1] - Mn[rs]);
                    lsum[rs] += p0 + p1;
                    const int row = r0 + mi * 16 + hf * 8;
                    const int col = wn * 32 + ni * 8 + ((lane & 3) << 1);
                    const int panel = col >> 6, cc = col & 63;
                    unsigned hw, lw;
                    split_pair(p0, p1, hw, lw);
                    uint32_t off = SWZ((row << 7) + cc * 2);
                    *(unsigned*)(smem + OFF_P + panel * 8192 + off) = hw;
                    *(unsigned*)(smem + OFF_P + 16384 + panel * 8192 + off) = lw;
                }
#pragma unroll
        for (int x = 1; x <= 2; x <<= 1)
#pragma unroll
            for (int rs = 0; rs < 4; rs++)
                lsum[rs] += __shfl_xor_sync(0xffffffffu, lsum[rs], x);
        if ((lane & 3) == 0) {
#pragma unroll
            for (int rs = 0; rs < 4; rs++)
                lred[wn * 64 + r0 + (rs >> 1) * 16 + (rs & 1) * 8] = lsum[rs];
        }
        // rescale O
#pragma unroll
        for (int mi = 0; mi < 2; mi++)
#pragma unroll
            for (int ni = 0; ni < 16; ni++)
#pragma unroll
                for (int v = 0; v < 4; v++)
                    accO[mi][ni][v] *= alpha[mi * 2 + (v >> 1)];
        __syncthreads();
        if (wn == 0 && (lane & 3) == 0) {
#pragma unroll
            for (int rs = 0; rs < 4; rs++) {
                const int r = r0 + (rs >> 1) * 16 + (rs & 1) * 8;
                sm_m[r] = Mn[rs];
                sm_l[r] = sm_l[r] * alpha[rs] +
                          (lred[r] + lred[64 + r] + lred[128 + r] + lred[192 + r]);
            }
        }

        // ---- PV: O += P @ V over 8 token-chunks of 16, double-buffered ----
        issue_V_chunk(sb + OFF_VBUF + VSTAGE, t, Vh0 + (size_t)16 * Ff, Vl0 + (size_t)16 * Ff);
        CP_COMMIT();
        for (int vc = 0; vc < 8; vc++) {
            if (vc < 7) CP_WAIT1(); else CP_WAIT0();
            __syncthreads();
            pv_mma_chunk(sb, sb + OFF_VBUF + (vc & 1) * VSTAGE, vc, lane, wm, wn, accO);
            __syncthreads();
            if (vc + 2 < 8) {
                issue_V_chunk(sb + OFF_VBUF + (vc & 1) * VSTAGE, t,
                              Vh0 + (size_t)(vc + 2) * 16 * Ff,
                              Vl0 + (size_t)(vc + 2) * 16 * Ff);
                CP_COMMIT();
            }
        }
    }

    __syncthreads();
    float invl[4];
#pragma unroll
    for (int rs = 0; rs < 4; rs++)
        invl[rs] = 1.0f / sm_l[r0 + (rs >> 1) * 16 + (rs & 1) * 8];
#pragma unroll
    for (int mi = 0; mi < 2; mi++)
#pragma unroll
        for (int ni = 0; ni < 16; ni++)
#pragma unroll
            for (int hf = 0; hf < 2; hf++) {
                const int rs = mi * 2 + hf;
                const int row = i0 + r0 + mi * 16 + hf * 8;
                const int col = wn * 128 + ni * 8 + ((lane & 3) << 1);
                float2 o = make_float2(accO[mi][ni][hf * 2] * invl[rs],
                                       accO[mi][ni][hf * 2 + 1] * invl[rs]);
                *(float2*)&g_YH[((size_t)bh * Nseq + row) * Dm + col] = o;
            }
}

// ======================= 5) head-sum + QuickGELU + split ====================
__global__ __launch_bounds__(256) void reduce_kernel() {
    int idx = blockIdx.x * 256 + threadIdx.x;
    int m = idx >> 7;
    int c4 = (idx & 127) * 4;
    int b = m >> 11, n = m & (Nseq - 1);
    float4 s = make_float4(0.f, 0.f, 0.f, 0.f);
#pragma unroll
    for (int h = 0; h < Hh; h++) {
        const float4 v = *(const float4*)(g_YH + (size_t)((b * Hh + h) * Nseq + n) * Dm + c4);
        s.x += v.x; s.y += v.y; s.z += v.z; s.w += v.w;
    }
    s.x = s.x / (1.f + expf(-1.702f * s.x));
    s.y = s.y / (1.f + expf(-1.702f * s.y));
    s.z = s.z / (1.f + expf(-1.702f * s.z));
    s.w = s.w / (1.f + expf(-1.702f * s.w));
    unsigned h0, l0, h1, l1;
    split_pair(s.x, s.y, h0, l0);
    split_pair(s.z, s.w, h1, l1);
    *(uint2*)(g_Gh + (size_t)m * Dm + c4) = make_uint2(h0, h1);
    *(uint2*)(g_Gl + (size_t)m * Dm + c4) = make_uint2(l0, l1);
}

// ======================= 6) output projection ===============================
__global__ __launch_bounds__(256) void mm_out_kernel(const float* __restrict__ bo,
                                                     float* __restrict__ Outp) {
    extern __shared__ __align__(128) char smem[];
    uint32_t sb = smem_to_u32(smem);
    const int bm = blockIdx.y * 128, bn = blockIdx.x * 128;
    const __nv_bfloat16* Ah = g_Gh + (size_t)bm * Dm;
    const __nv_bfloat16* Al = g_Gl + (size_t)bm * Dm;
    const __nv_bfloat16* Bh = g_WoTh + (size_t)bn * Dm;
    const __nv_bfloat16* Bl = g_WoTl + (size_t)bn * Dm;
    float acc[4][4][4];
    gemm_mma(Ah, Al, Dm, Bh, Bl, Dm, Dm, sb, acc);

    const int t = threadIdx.x, lane = t & 31, w = t >> 5, wm = w & 1, wn = w >> 1;
#pragma unroll
    for (int mi = 0; mi < 4; mi++)
#pragma unroll
        for (int ni = 0; ni < 4; ni++) {
            int m = bm + wm * 64 + mi * 16 + (lane >> 2);
            int c = bn + wn * 32 + ni * 8 + ((lane & 3) << 1);
            float b0 = bo[c], b1 = bo[c + 1];
            *(float2*)&Outp[(size_t)m * Dm + c] =
                make_float2(acc[mi][ni][0] + b0, acc[mi][ni][1] + b1);
            *(float2*)&Outp[(size_t)(m + 8) * Dm + c] =
                make_float2(acc[mi][ni][2] + b0, acc[mi][ni][3] + b1);
        }
}

// ======================= launch =============================================
extern "C" void kernel_launch(void* const* d_in, const int* in_sizes, int n_in,
                              void* d_out, int out_size)
{
    const float* x    = (const float*)d_in[0];
    const float* cosr = (const float*)d_in[1];
    const float* sinr = (const float*)d_in[2];
    // d_in[3] = target_mask (causal tril; handled analytically)
    const float* Wq   = (const float*)d_in[4];
    const float* Wk   = (const float*)d_in[5];
    const float* Wv   = (const float*)d_in[6];
    const float* bv   = (const float*)d_in[7];
    const float* Wo   = (const float*)d_in[8];
    const float* bo   = (const float*)d_in[9];
    float* out = (float*)d_out;

    cudaFuncSetAttribute(mm_proj_kernel,  cudaFuncAttributeMaxDynamicSharedMemorySize, SMEM_BYTES);
    cudaFuncSetAttribute(fused_attn_kernel, cudaFuncAttributeMaxDynamicSharedMemorySize, FUSED_SMEM);
    cudaFuncSetAttribute(mm_out_kernel,   cudaFuncAttributeMaxDynamicSharedMemorySize, SMEM_BYTES);

    __nv_bfloat16 *wth, *wtl, *woth, *wotl;
    cudaGetSymbolAddress((void**)&wth,  g_WTh);
    cudaGetSymbolAddress((void**)&wtl,  g_WTl);
    cudaGetSymbolAddress((void**)&woth, g_WoTh);
    cudaGetSymbolAddress((void**)&wotl, g_WoTl);

    xc_kernel<<<2048, 256>>>(x);
    wt_kernel<<<dim3(128, 16), dim3(32, 32)>>>(Wq, wth + 0 * (size_t)Ff * Dm,
                                               wtl + 0 * (size_t)Ff * Dm, Dm, Ff);
    wt_kernel<<<dim3(128, 16), dim3(32, 32)>>>(Wk, wth + 1 * (size_t)Ff * Dm,
                                               wtl + 1 * (size_t)Ff * Dm, Dm, Ff);
    wt_kernel<<<dim3(128, 16), dim3(32, 32)>>>(Wv, wth + 2 * (size_t)Ff * Dm,
                                               wtl + 2 * (size_t)Ff * Dm, Dm, Ff);
    wt_kernel<<<dim3(16, 16), dim3(32, 32)>>>(Wo, woth, wotl, Dm, Dm);

    mm_proj_kernel<<<dim3(32, 32, 3), 256, SMEM_BYTES>>>(cosr, sinr, bv);
    fused_attn_kernel<<<dim3(32, BH), 256, FUSED_SMEM>>>();
    reduce_kernel<<<2048, 256>>>();
    mm_out_kernel<<<dim3(4, 32), 256, SMEM_BYTES>>>(bo, out);
}